// round 4
// baseline (speedup 1.0000x reference)
#include <cuda_runtime.h>

// out[b,c] = exp( sum_s x[b, chunk_map[c,s]] * wSupp[c,s] )
// B=4096, NCLASS=1000, NSUPP=64, NCHUNK=4096

#define NCLASS 1000
#define NSUPP  64
#define NCHUNK 4096
#define BATCH  4096
#define NB     8       // batch rows per CTA
#define THREADS 1024
#define PACK_T  64     // pack threads per CTA (32 KB static smem scratch)

// Packed (idx, w) pairs, transposed to [s2][class] so the hot loop's LDG is
// coalesced across lanes (lane = class). Each int4 holds 2 s-steps.
//
// Conflict-free schedule: an LDS.128 phase is 8 lanes = 8 consecutive
// classes. At step t, class c *wants* to read bank group (t + c) & 7; each
// entry of group g = idx&7 is therefore placed in one of the 8 slots
// t ≡ (g - c) (mod 8). When that works for all 8 classes of a phase, every
// step reads 8 distinct bank groups -> zero LDS conflicts. Overflow entries
// (group count > 8) spill into leftover slots (~13% of entries).
__device__ int4 g_packed[(NSUPP / 2) * NCLASS];

__global__ void pack_kernel(const float* __restrict__ w,
                            const int* __restrict__ cmap) {
    __shared__ int2 S[PACK_T][NSUPP];   // per-thread schedule scratch (32 KB)
    int c = blockIdx.x * PACK_T + threadIdx.x;
    if (c >= NCLASS) return;
    int2* s = S[threadIdx.x];

    // empty-mark all slots
    for (int t = 0; t < NSUPP; ++t) s[t].x = -1;

    const int*   row  = cmap + c * NSUPP;
    const float* wrow = w + c * NSUPP;

    // pass 1: place each entry in a preferred slot for its bank group
    unsigned long long placed = 0ull;
    for (int e = 0; e < NSUPP; ++e) {
        int idx = row[e];
        int bt  = ((idx & 7) - c) & 7;   // preferred slot residue mod 8
        for (int k = 0; k < 8; ++k) {
            int t = bt + 8 * k;
            if (s[t].x == -1) {
                s[t] = make_int2(idx, __float_as_int(wrow[e]));
                placed |= 1ull << e;
                break;
            }
        }
    }
    // pass 2: spill overflow entries into remaining empty slots
    int t = 0;
    for (int e = 0; e < NSUPP; ++e) {
        if ((placed >> e) & 1ull) continue;
        while (s[t].x != -1) ++t;
        s[t] = make_int2(row[e], __float_as_int(wrow[e]));
        ++t;
    }
    // emit packed pairs, transposed [s2][class]
    for (int j2 = 0; j2 < NSUPP / 2; ++j2) {
        int2 e0 = s[2 * j2];
        int2 e1 = s[2 * j2 + 1];
        g_packed[j2 * NCLASS + c] = make_int4(e0.x, e0.y, e1.x, e1.y);
    }
}

__global__ void __launch_bounds__(THREADS, 1)
supp_kernel(const float* __restrict__ x, float* __restrict__ out) {
    // Two separate float4 tiles so each gather's bank group is idx&7
    // (full 8-bin spread) and tile-fill STS.128 is conflict-free.
    extern __shared__ float4 smem[];
    float4* xs_lo = smem;           // x[b0..b0+3][idx]
    float4* xs_hi = smem + NCHUNK;  // x[b0+4..b0+7][idx]

    const int b0 = blockIdx.x * NB;

    // --- Stage x tile: 8 rows x 4096 floats = 128 KB ---
    for (int i = threadIdx.x; i < NCHUNK; i += THREADS) {
        const float* xb = x + (size_t)b0 * NCHUNK + i;
        float t0 = xb[0 * NCHUNK];
        float t1 = xb[1 * NCHUNK];
        float t2 = xb[2 * NCHUNK];
        float t3 = xb[3 * NCHUNK];
        float t4 = xb[4 * NCHUNK];
        float t5 = xb[5 * NCHUNK];
        float t6 = xb[6 * NCHUNK];
        float t7 = xb[7 * NCHUNK];
        xs_lo[i] = make_float4(t0, t1, t2, t3);
        xs_hi[i] = make_float4(t4, t5, t6, t7);
    }
    __syncthreads();

    // --- Gather + dot: thread = class, 8 batch rows per thread ---
    // (class c at phase-lane c%8; schedule makes the 8 lanes of each phase
    //  read ~distinct bank groups at every step)
    for (int c = threadIdx.x; c < NCLASS; c += THREADS) {
        float a0 = 0.f, a1 = 0.f, a2 = 0.f, a3 = 0.f;
        float a4 = 0.f, a5 = 0.f, a6 = 0.f, a7 = 0.f;
#pragma unroll 2
        for (int s2 = 0; s2 < NSUPP / 2; ++s2) {
            int4 p = g_packed[s2 * NCLASS + c];  // coalesced LDG.128

            float w0 = __int_as_float(p.y);
            float4 lo = xs_lo[p.x];
            float4 hi = xs_hi[p.x];
            a0 = fmaf(lo.x, w0, a0);
            a1 = fmaf(lo.y, w0, a1);
            a2 = fmaf(lo.z, w0, a2);
            a3 = fmaf(lo.w, w0, a3);
            a4 = fmaf(hi.x, w0, a4);
            a5 = fmaf(hi.y, w0, a5);
            a6 = fmaf(hi.z, w0, a6);
            a7 = fmaf(hi.w, w0, a7);

            float w1 = __int_as_float(p.w);
            lo = xs_lo[p.z];
            hi = xs_hi[p.z];
            a0 = fmaf(lo.x, w1, a0);
            a1 = fmaf(lo.y, w1, a1);
            a2 = fmaf(lo.z, w1, a2);
            a3 = fmaf(lo.w, w1, a3);
            a4 = fmaf(hi.x, w1, a4);
            a5 = fmaf(hi.y, w1, a5);
            a6 = fmaf(hi.z, w1, a6);
            a7 = fmaf(hi.w, w1, a7);
        }

        float* o = out + (size_t)b0 * NCLASS + c;
        o[0 * NCLASS] = __expf(a0);
        o[1 * NCLASS] = __expf(a1);
        o[2 * NCLASS] = __expf(a2);
        o[3 * NCLASS] = __expf(a3);
        o[4 * NCLASS] = __expf(a4);
        o[5 * NCLASS] = __expf(a5);
        o[6 * NCLASS] = __expf(a6);
        o[7 * NCLASS] = __expf(a7);
    }
}

extern "C" void kernel_launch(void* const* d_in, const int* in_sizes, int n_in,
                              void* d_out, int out_size) {
    const float* x    = (const float*)d_in[0];  // [4096, 4096] f32
    const float* w    = (const float*)d_in[1];  // [1000, 64]   f32
    const int*   cmap = (const int*)d_in[2];    // [1000, 64]   i32
    float*       out  = (float*)d_out;          // [4096, 1000] f32

    (void)in_sizes; (void)n_in; (void)out_size;

    static const size_t smem_bytes = 2 * NCHUNK * sizeof(float4);  // 128 KB
    cudaFuncSetAttribute(supp_kernel,
                         cudaFuncAttributeMaxDynamicSharedMemorySize,
                         (int)smem_bytes);

    pack_kernel<<<(NCLASS + PACK_T - 1) / PACK_T, PACK_T>>>(w, cmap);
    supp_kernel<<<BATCH / NB, THREADS, smem_bytes>>>(x, out);
}

// round 5
// speedup vs baseline: 1.5252x; 1.5252x over previous
#include <cuda_runtime.h>

// out[b,c] = exp( sum_s x[b, chunk_map[c,s]] * wSupp[c,s] )
// B=4096, NCLASS=1000, NSUPP=64, NCHUNK=4096

#define NCLASS 1000
#define NSUPP  64
#define NCHUNK 4096
#define BATCH  4096
#define NB     8       // batch rows per CTA
#define THREADS 1024
#define PACK_T  64     // pack threads per CTA

// Packed (idx, w) pairs, transposed to [s2][class] so the hot loop's LDG is
// coalesced across lanes (lane = class). Each int4 holds 2 s-steps.
//
// Conflict-free schedule: an LDS.128 phase is 8 lanes = 8 consecutive
// classes. At step t, class c *wants* to read bank group (t + c) & 7; each
// entry of group g = idx&7 is placed in one of the 8 slots
// t ≡ (g - c) (mod 8). When that works for all 8 classes of a phase, every
// step reads 8 distinct bank groups -> zero LDS conflicts. Overflow entries
// spill into leftover slots (~13% of entries).
__device__ int4 g_packed[(NSUPP / 2) * NCLASS];

__global__ void pack_kernel(const float* __restrict__ w,
                            const int* __restrict__ cmap) {
    // slot->entry table, TRANSPOSED [slot][tid] so equal-slot accesses from
    // the 32 lanes land in different banks (<=2-way for int2).
    __shared__ int2 S[NSUPP][PACK_T];
    int c = blockIdx.x * PACK_T + threadIdx.x;
    if (c >= NCLASS) return;
    const int tid = threadIdx.x;

    const int*   row  = cmap + c * NSUPP;
    const float* wrow = w + c * NSUPP;

    const unsigned long long PRE = 0x0101010101010101ull;
    unsigned long long occ = 0ull;      // slot occupancy bitmask
    unsigned long long placedmask = 0ull;

    // pass 1: register-bitmask placement into preferred slots
    for (int e = 0; e < NSUPP; ++e) {
        int idx = row[e];
        int r = ((idx & 7) - c) & 7;                  // preferred residue
        unsigned long long freep = (PRE << r) & ~occ; // free preferred slots
        if (freep) {
            int slot = __ffsll((long long)freep) - 1;
            occ |= 1ull << slot;
            placedmask |= 1ull << e;
            S[slot][tid] = make_int2(idx, __float_as_int(wrow[e]));
        }
    }
    // pass 2: spill unplaced entries into lowest free slots
    for (int e = 0; e < NSUPP; ++e) {
        if ((placedmask >> e) & 1ull) continue;
        unsigned long long freeall = ~occ;
        int slot = __ffsll((long long)freeall) - 1;
        occ |= 1ull << slot;
        S[slot][tid] = make_int2(row[e], __float_as_int(wrow[e]));
    }
    // emit packed pairs, transposed [s2][class]
    for (int j2 = 0; j2 < NSUPP / 2; ++j2) {
        int2 e0 = S[2 * j2][tid];
        int2 e1 = S[2 * j2 + 1][tid];
        g_packed[j2 * NCLASS + c] = make_int4(e0.x, e0.y, e1.x, e1.y);
    }
}

__global__ void __launch_bounds__(THREADS, 1)
supp_kernel(const float* __restrict__ x, float* __restrict__ out) {
    // Two separate float4 tiles so each gather's bank group is idx&7
    // (full 8-bin spread) and tile-fill STS.128 is conflict-free.
    extern __shared__ float4 smem[];
    float4* xs_lo = smem;           // x[b0..b0+3][idx]
    float4* xs_hi = smem + NCHUNK;  // x[b0+4..b0+7][idx]

    const int b0 = blockIdx.x * NB;

    // --- Stage x tile: 8 rows x 4096 floats = 128 KB ---
    for (int i = threadIdx.x; i < NCHUNK; i += THREADS) {
        const float* xb = x + (size_t)b0 * NCHUNK + i;
        float t0 = xb[0 * NCHUNK];
        float t1 = xb[1 * NCHUNK];
        float t2 = xb[2 * NCHUNK];
        float t3 = xb[3 * NCHUNK];
        float t4 = xb[4 * NCHUNK];
        float t5 = xb[5 * NCHUNK];
        float t6 = xb[6 * NCHUNK];
        float t7 = xb[7 * NCHUNK];
        xs_lo[i] = make_float4(t0, t1, t2, t3);
        xs_hi[i] = make_float4(t4, t5, t6, t7);
    }
    __syncthreads();

    // --- Gather + dot: thread = class, 8 batch rows per thread ---
    // (class c at phase-lane c%8; schedule makes the 8 lanes of each phase
    //  read ~distinct bank groups at every step)
    for (int c = threadIdx.x; c < NCLASS; c += THREADS) {
        float a0 = 0.f, a1 = 0.f, a2 = 0.f, a3 = 0.f;
        float a4 = 0.f, a5 = 0.f, a6 = 0.f, a7 = 0.f;
#pragma unroll 2
        for (int s2 = 0; s2 < NSUPP / 2; ++s2) {
            int4 p = g_packed[s2 * NCLASS + c];  // coalesced LDG.128

            float w0 = __int_as_float(p.y);
            float4 lo = xs_lo[p.x];
            float4 hi = xs_hi[p.x];
            a0 = fmaf(lo.x, w0, a0);
            a1 = fmaf(lo.y, w0, a1);
            a2 = fmaf(lo.z, w0, a2);
            a3 = fmaf(lo.w, w0, a3);
            a4 = fmaf(hi.x, w0, a4);
            a5 = fmaf(hi.y, w0, a5);
            a6 = fmaf(hi.z, w0, a6);
            a7 = fmaf(hi.w, w0, a7);

            float w1 = __int_as_float(p.w);
            lo = xs_lo[p.z];
            hi = xs_hi[p.z];
            a0 = fmaf(lo.x, w1, a0);
            a1 = fmaf(lo.y, w1, a1);
            a2 = fmaf(lo.z, w1, a2);
            a3 = fmaf(lo.w, w1, a3);
            a4 = fmaf(hi.x, w1, a4);
            a5 = fmaf(hi.y, w1, a5);
            a6 = fmaf(hi.z, w1, a6);
            a7 = fmaf(hi.w, w1, a7);
        }

        float* o = out + (size_t)b0 * NCLASS + c;
        o[0 * NCLASS] = __expf(a0);
        o[1 * NCLASS] = __expf(a1);
        o[2 * NCLASS] = __expf(a2);
        o[3 * NCLASS] = __expf(a3);
        o[4 * NCLASS] = __expf(a4);
        o[5 * NCLASS] = __expf(a5);
        o[6 * NCLASS] = __expf(a6);
        o[7 * NCLASS] = __expf(a7);
    }
}

extern "C" void kernel_launch(void* const* d_in, const int* in_sizes, int n_in,
                              void* d_out, int out_size) {
    const float* x    = (const float*)d_in[0];  // [4096, 4096] f32
    const float* w    = (const float*)d_in[1];  // [1000, 64]   f32
    const int*   cmap = (const int*)d_in[2];    // [1000, 64]   i32
    float*       out  = (float*)d_out;          // [4096, 1000] f32

    (void)in_sizes; (void)n_in; (void)out_size;

    static const size_t smem_bytes = 2 * NCHUNK * sizeof(float4);  // 128 KB
    cudaFuncSetAttribute(supp_kernel,
                         cudaFuncAttributeMaxDynamicSharedMemorySize,
                         (int)smem_bytes);

    pack_kernel<<<(NCLASS + PACK_T - 1) / PACK_T, PACK_T>>>(w, cmap);
    supp_kernel<<<BATCH / NB, THREADS, smem_bytes>>>(x, out);
}